// round 9
// baseline (speedup 1.0000x reference)
#include <cuda_runtime.h>
#include <cstdint>

#define NBATCH 256
#define NTIME  256
#define NS     512   // state size
#define NE     128   // embedding
#define NALPH  128   // alphabet / output
#define FAN    640   // NE + NS
#define BT     (NBATCH * NTIME)

#define NROWT  16    // row tiles (16 batch rows each) = clusters
#define NCOLT  8     // col tiles (64 state cols each) = CTAs per cluster

typedef unsigned long long u64;

// ---- scratch (static __device__: allocation-free per harness rules) ----
__device__ float g_fin[BT * NS];          // fin[(b*NTIME+t)*NS + n]
__device__ float g_states[BT * NS];       // states[(b*NTIME+t)*NS + n]

// ---- packed fp32x2 helpers (Blackwell FFMA2) ----
__device__ __forceinline__ void fma2(u64& d, u64 a, u64 b) {
    asm("fma.rn.f32x2 %0, %1, %2, %0;" : "+l"(d) : "l"(a), "l"(b));
}
__device__ __forceinline__ float hadd2(u64 v) {
    float lo, hi;
    asm("mov.b64 {%0,%1}, %2;" : "=f"(lo), "=f"(hi) : "l"(v));
    return lo + hi;
}

// ---- DSMEM store: write v to the same smem offset in cluster CTA `rank` ----
__device__ __forceinline__ void st_cluster(uint32_t saddr, int rank, float v) {
    uint32_t r;
    asm volatile("mapa.shared::cluster.u32 %0, %1, %2;"
                 : "=r"(r) : "r"(saddr), "r"(rank));
    asm volatile("st.shared::cluster.f32 [%0], %1;"
                 :: "r"(r), "f"(v) : "memory");
}

// =====================================================================
// Phase 1: fin[bt][n] = dot(emb[w[bt]], W_in[n][0:128]) + b_in[n]
// =====================================================================
__global__ void __launch_bounds__(256)
fin_kernel(const int* __restrict__ w,
           const float* __restrict__ emb,
           const float* __restrict__ W_in,
           const float* __restrict__ b_in) {
    __shared__ int   widx[64];
    __shared__ float As[64 * 36];
    __shared__ float Bs[64 * 33];

    int tid = threadIdx.x;
    int tx = tid & 15, ty = tid >> 4;
    int bt0 = blockIdx.x * 64;
    int n0  = blockIdx.y * 64;

    if (tid < 64) widx[tid] = w[bt0 + tid];
    __syncthreads();

    float acc[4][4] = {};

    for (int kc = 0; kc < NE; kc += 32) {
        for (int s = tid; s < 512; s += 256) {
            int row = s >> 3, q = (s & 7) << 2;
            float4 v = *(const float4*)&emb[widx[row] * NE + kc + q];
            *(float4*)&As[row * 36 + q] = v;
        }
        for (int s = tid; s < 512; s += 256) {
            int row = s >> 3, q = (s & 7) << 2;
            float4 v = *(const float4*)&W_in[(n0 + row) * FAN + kc + q];
            float* d = &Bs[row * 33 + q];
            d[0] = v.x; d[1] = v.y; d[2] = v.z; d[3] = v.w;
        }
        __syncthreads();
        #pragma unroll
        for (int k = 0; k < 32; ++k) {
            float a[4], b[4];
            #pragma unroll
            for (int i = 0; i < 4; ++i) a[i] = As[(ty + 16 * i) * 36 + k];
            #pragma unroll
            for (int j = 0; j < 4; ++j) b[j] = Bs[(tx + 16 * j) * 33 + k];
            #pragma unroll
            for (int i = 0; i < 4; ++i)
                #pragma unroll
                for (int j = 0; j < 4; ++j)
                    acc[i][j] = fmaf(a[i], b[j], acc[i][j]);
        }
        __syncthreads();
    }

    #pragma unroll
    for (int i = 0; i < 4; ++i) {
        int r = bt0 + ty + 16 * i;
        #pragma unroll
        for (int j = 0; j < 4; ++j) {
            int c = n0 + tx + 16 * j;
            g_fin[r * NS + c] = acc[i][j] + b_in[c];
        }
    }
}

// =====================================================================
// Phase 2: persistent recurrent kernel, 8-CTA clusters.
// Cluster = one rowtile (16 batch rows); CTA rank = coltile (64 cols).
// State exchange is producer-push over DSMEM (st.shared::cluster) into
// double-buffered As; ONE barrier.cluster per step (release/acquire).
// No L2 fences, atomics, polls, or staging loads. No __syncthreads in
// the step loop.
// =====================================================================
__global__ void __launch_bounds__(256, 1) __cluster_dims__(NCOLT, 1, 1)
rnn_kernel(const float* __restrict__ W_in) {
    extern __shared__ float sm[];
    float* Bs = sm;                      // [64][516]  W_s slice
    float* A0 = sm + 64 * 516;           // state buf 0: [16][520]
    float* A1 = A0 + 16 * 520;           // state buf 1: [16][520]

    const int tid  = threadIdx.x;
    const int wrp  = tid >> 5;           // 0..7
    const int lane = tid & 31;
    const int tx   = lane & 7;           // col within warp's 8-col strip
    const int tyq  = lane >> 3;          // row quadrant 0..3
    const int rowtile = blockIdx.x >> 3; // 0..15 (cluster id)
    const int coltile = blockIdx.x & 7;  // 0..7  (cluster rank)
    const int rb0 = rowtile * 16;
    const int cb0 = coltile * 64;

    // Load W_s slice once: Bs[n][k] = W_in[(cb0+n)*FAN + NE + k]
    for (int s = tid; s < 64 * 128; s += 256) {
        int row = s >> 7, q = (s & 127) << 2;
        float4 v = *(const float4*)&W_in[(cb0 + row) * FAN + NE + q];
        *(float4*)&Bs[row * 516 + q] = v;
    }
    __syncthreads();

    const uint32_t a0_u32 = (uint32_t)__cvta_generic_to_shared(A0);
    const uint32_t a1_u32 = (uint32_t)__cvta_generic_to_shared(A1);

    const int mycol = 8 * wrp + tx;      // 0..63 within this CTA's strip
    const float* bp = Bs + mycol * 516;

    const int cg = cb0 + mycol;          // global state col of this thread
    int rr[4];
    rr[0] = rb0 + tyq;     rr[1] = rb0 + tyq + 4;
    rr[2] = rb0 + tyq + 8; rr[3] = rb0 + tyq + 12;

    // prefetch fin for t = 0
    float ffin[4];
    #pragma unroll
    for (int i = 0; i < 4; ++i)
        ffin[i] = __ldcg(&g_fin[(rr[i] * NTIME + 0) * NS + cg]);

    for (int t = 0; t < NTIME; ++t) {
        const int sel = t & 1;
        u64 acc[4] = {};

        if (t > 0) {
            const float* Ab  = sel ? A1 : A0;     // state[t-1]
            const float* ap0 = Ab + (tyq)      * 520;
            const float* ap1 = Ab + (tyq + 4)  * 520;
            const float* ap2 = Ab + (tyq + 8)  * 520;
            const float* ap3 = Ab + (tyq + 12) * 520;
            #pragma unroll 4
            for (int k = 0; k < NS; k += 4) {
                ulonglong2 B  = *(const ulonglong2*)(bp  + k);
                ulonglong2 A0v = *(const ulonglong2*)(ap0 + k);
                ulonglong2 A1v = *(const ulonglong2*)(ap1 + k);
                ulonglong2 A2v = *(const ulonglong2*)(ap2 + k);
                ulonglong2 A3v = *(const ulonglong2*)(ap3 + k);
                fma2(acc[0], A0v.x, B.x); fma2(acc[0], A0v.y, B.y);
                fma2(acc[1], A1v.x, B.x); fma2(acc[1], A1v.y, B.y);
                fma2(acc[2], A2v.x, B.x); fma2(acc[2], A2v.y, B.y);
                fma2(acc[3], A3v.x, B.x); fma2(acc[3], A3v.y, B.y);
            }
        }

        // ---- epilogue: v = tanh(acc + fin_t) ----
        float v[4];
        #pragma unroll
        for (int i = 0; i < 4; ++i) {
            v[i] = tanhf(hadd2(acc[i]) + ffin[i]);
            g_states[(rr[i] * NTIME + t) * NS + cg] = v[i];   // log (out_kernel only)
        }

        if (t + 1 < NTIME) {
            // push state[t] into ALL 8 cluster CTAs' write buffer (sel^1)
            const uint32_t wb = sel ? a0_u32 : a1_u32;
            #pragma unroll
            for (int i = 0; i < 4; ++i) {
                uint32_t off = wb + (uint32_t)(((tyq + 4 * i) * 520 + cg) << 2);
                #pragma unroll
                for (int p = 0; p < NCOLT; ++p)
                    st_cluster(off, p, v[i]);
            }
            // one cluster barrier per step: arrive (release), prefetch
            // fin(t+1) in the gap, wait (acquire)
            asm volatile("barrier.cluster.arrive.aligned;" ::: "memory");
            #pragma unroll
            for (int i = 0; i < 4; ++i)
                ffin[i] = __ldcg(&g_fin[(rr[i] * NTIME + t + 1) * NS + cg]);
            asm volatile("barrier.cluster.wait.aligned;" ::: "memory");
        }
    }
}

// =====================================================================
// Phase 3: y[bt][a] = dot(states[bt], W_out[a]) + b_out[a]
// =====================================================================
__global__ void __launch_bounds__(256)
out_kernel(const float* __restrict__ W_out,
           const float* __restrict__ b_out,
           float* __restrict__ y) {
    __shared__ float As[64 * 36];
    __shared__ float Bs[64 * 33];

    int tid = threadIdx.x;
    int tx = tid & 15, ty = tid >> 4;
    int bt0 = blockIdx.x * 64;
    int a0  = blockIdx.y * 64;

    float acc[4][4] = {};

    for (int kc = 0; kc < NS; kc += 32) {
        for (int s = tid; s < 512; s += 256) {
            int row = s >> 3, q = (s & 7) << 2;
            float4 v = *(const float4*)&g_states[(bt0 + row) * NS + kc + q];
            *(float4*)&As[row * 36 + q] = v;
        }
        for (int s = tid; s < 512; s += 256) {
            int row = s >> 3, q = (s & 7) << 2;
            float4 v = *(const float4*)&W_out[(a0 + row) * NS + kc + q];
            float* d = &Bs[row * 33 + q];
            d[0] = v.x; d[1] = v.y; d[2] = v.z; d[3] = v.w;
        }
        __syncthreads();
        #pragma unroll
        for (int k = 0; k < 32; ++k) {
            float a[4], b[4];
            #pragma unroll
            for (int i = 0; i < 4; ++i) a[i] = As[(ty + 16 * i) * 36 + k];
            #pragma unroll
            for (int j = 0; j < 4; ++j) b[j] = Bs[(tx + 16 * j) * 33 + k];
            #pragma unroll
            for (int i = 0; i < 4; ++i)
                #pragma unroll
                for (int j = 0; j < 4; ++j)
                    acc[i][j] = fmaf(a[i], b[j], acc[i][j]);
        }
        __syncthreads();
    }

    #pragma unroll
    for (int i = 0; i < 4; ++i) {
        int r = bt0 + ty + 16 * i;
        #pragma unroll
        for (int j = 0; j < 4; ++j) {
            int c = a0 + tx + 16 * j;
            y[r * NALPH + c] = acc[i][j] + b_out[c];
        }
    }
}

// =====================================================================
// launch
// =====================================================================
extern "C" void kernel_launch(void* const* d_in, const int* in_sizes, int n_in,
                              void* d_out, int out_size) {
    const int*   w     = (const int*)  d_in[0];
    const float* emb   = (const float*)d_in[1];
    const float* W_in  = (const float*)d_in[2];
    const float* b_in  = (const float*)d_in[3];
    const float* W_out = (const float*)d_in[4];
    const float* b_out = (const float*)d_in[5];
    float* y = (float*)d_out;

    // rnn: 64*516 (W_s) + 2*16*520 (double-buffered state) floats = ~194 KB
    size_t rnn_smem = (size_t)(64 * 516 + 2 * 16 * 520) * sizeof(float);
    cudaFuncSetAttribute(rnn_kernel,
                         cudaFuncAttributeMaxDynamicSharedMemorySize,
                         (int)rnn_smem);

    fin_kernel<<<dim3(BT / 64, NS / 64), 256>>>(w, emb, W_in, b_in);
    rnn_kernel<<<128, 256, rnn_smem>>>(W_in);
    out_kernel<<<dim3(BT / 64, NALPH / 64), 256>>>(W_out, b_out, y);
}

// round 10
// speedup vs baseline: 1.8616x; 1.8616x over previous
#include <cuda_runtime.h>
#include <cstdint>

#define NBATCH 256
#define NTIME  256
#define NS     512   // state size
#define NE     128   // embedding
#define NALPH  128   // alphabet / output
#define FAN    640   // NE + NS
#define BT     (NBATCH * NTIME)

#define NROWT  16    // row tiles (16 batch rows each)
#define NCOLT  8     // col tiles (64 state cols each)
#define BARPAD 32    // ints per barrier counter -> one 128B L2 line each

typedef unsigned long long u64;

// ---- scratch (static __device__: allocation-free per harness rules) ----
__device__ float g_fin[BT * NS];          // fin[(b*NTIME+t)*NS + n]
__device__ float g_states[BT * NS];       // states[(b*NTIME+t)*NS + n]
__device__ int   g_bar[NTIME * NROWT * BARPAD];  // padded per-(step,rowtile) counters

// ---- packed fp32x2 helpers (Blackwell FFMA2) ----
__device__ __forceinline__ void fma2(u64& d, u64 a, u64 b) {
    asm("fma.rn.f32x2 %0, %1, %2, %0;" : "+l"(d) : "l"(a), "l"(b));
}
__device__ __forceinline__ float hadd2(u64 v) {
    float lo, hi;
    asm("mov.b64 {%0,%1}, %2;" : "=f"(lo), "=f"(hi) : "l"(v));
    return lo + hi;
}

// ---- release arrive / acquire poll (no separate membar needed) ----
__device__ __forceinline__ void arrive_release(int* p) {
    asm volatile("red.release.gpu.global.add.u32 [%0], 1;" :: "l"(p) : "memory");
}
__device__ __forceinline__ int ld_acq(const int* p) {
    int v;
    asm volatile("ld.acquire.gpu.global.b32 %0, [%1];" : "=r"(v) : "l"(p) : "memory");
    return v;
}

// =====================================================================
// reset: zero barrier counters (fresh per launch -> graph-replay safe)
// =====================================================================
__global__ void reset_kernel() {
    int i = blockIdx.x * blockDim.x + threadIdx.x;
    if (i < NTIME * NROWT * BARPAD) g_bar[i] = 0;
}

// =====================================================================
// Phase 1: fin[bt][n] = dot(emb[w[bt]], W_in[n][0:128]) + b_in[n]
// =====================================================================
__global__ void __launch_bounds__(256)
fin_kernel(const int* __restrict__ w,
           const float* __restrict__ emb,
           const float* __restrict__ W_in,
           const float* __restrict__ b_in) {
    __shared__ int   widx[64];
    __shared__ float As[64 * 36];
    __shared__ float Bs[64 * 33];

    int tid = threadIdx.x;
    int tx = tid & 15, ty = tid >> 4;
    int bt0 = blockIdx.x * 64;
    int n0  = blockIdx.y * 64;

    if (tid < 64) widx[tid] = w[bt0 + tid];
    __syncthreads();

    float acc[4][4] = {};

    for (int kc = 0; kc < NE; kc += 32) {
        for (int s = tid; s < 512; s += 256) {
            int row = s >> 3, q = (s & 7) << 2;
            float4 v = *(const float4*)&emb[widx[row] * NE + kc + q];
            *(float4*)&As[row * 36 + q] = v;
        }
        for (int s = tid; s < 512; s += 256) {
            int row = s >> 3, q = (s & 7) << 2;
            float4 v = *(const float4*)&W_in[(n0 + row) * FAN + kc + q];
            float* d = &Bs[row * 33 + q];
            d[0] = v.x; d[1] = v.y; d[2] = v.z; d[3] = v.w;
        }
        __syncthreads();
        #pragma unroll
        for (int k = 0; k < 32; ++k) {
            float a[4], b[4];
            #pragma unroll
            for (int i = 0; i < 4; ++i) a[i] = As[(ty + 16 * i) * 36 + k];
            #pragma unroll
            for (int j = 0; j < 4; ++j) b[j] = Bs[(tx + 16 * j) * 33 + k];
            #pragma unroll
            for (int i = 0; i < 4; ++i)
                #pragma unroll
                for (int j = 0; j < 4; ++j)
                    acc[i][j] = fmaf(a[i], b[j], acc[i][j]);
        }
        __syncthreads();
    }

    #pragma unroll
    for (int i = 0; i < 4; ++i) {
        int r = bt0 + ty + 16 * i;
        #pragma unroll
        for (int j = 0; j < 4; ++j) {
            int c = n0 + tx + 16 * j;
            g_fin[r * NS + c] = acc[i][j] + b_in[c];
        }
    }
}

// =====================================================================
// Phase 2: persistent recurrent kernel (R7 structure).
// 128 blocks: rowtile = bid>>3 (16 batch rows), coltile = bid&7 (64 cols).
// 256 threads; warp w owns cols [8w, 8w+8). Per-rowtile sync, with each
// (step,rowtile) counter on its OWN 128B line (kills L2 atomic-line
// serialization), release-arrive / acquire-poll (no membar.gpu).
// =====================================================================
__global__ void __launch_bounds__(256, 1)
rnn_kernel(const float* __restrict__ W_in) {
    extern __shared__ float sm[];
    float* Bs = sm;                 // [64][516]  W_s slice
    float* As = sm + 64 * 516;      // [16][520]  state tile

    const int tid  = threadIdx.x;
    const int wrp  = tid >> 5;      // 0..7
    const int lane = tid & 31;
    const int tx   = lane & 7;      // 0..7  (col within warp's 8-col strip)
    const int tyq  = lane >> 3;     // 0..3  (row quadrant)
    const int rowtile = blockIdx.x >> 3;   // 0..15
    const int coltile = blockIdx.x & 7;    // 0..7
    const int rb0 = rowtile * 16;
    const int cb0 = coltile * 64;

    // Load W_s slice once: Bs[n][k] = W_in[(cb0+n)*FAN + NE + k]
    for (int s = tid; s < 64 * 128; s += 256) {
        int row = s >> 7, q = (s & 127) << 2;
        float4 v = *(const float4*)&W_in[(cb0 + row) * FAN + NE + q];
        *(float4*)&Bs[row * 516 + q] = v;
    }
    __syncthreads();

    const int mycol = 8 * wrp + tx;             // 0..63 within tile
    const float* bp  = Bs + mycol * 516;
    const float* ap0 = As + (tyq)      * 520;
    const float* ap1 = As + (tyq + 4)  * 520;
    const float* ap2 = As + (tyq + 8)  * 520;
    const float* ap3 = As + (tyq + 12) * 520;

    const int c  = cb0 + mycol;                 // global state col
    int rr[4];
    rr[0] = rb0 + tyq; rr[1] = rb0 + tyq + 4;
    rr[2] = rb0 + tyq + 8; rr[3] = rb0 + tyq + 12;

    // prefetch fin for t = 0
    float ffin[4];
    #pragma unroll
    for (int i = 0; i < 4; ++i)
        ffin[i] = __ldcg(&g_fin[(rr[i] * NTIME + 0) * NS + c]);

    for (int t = 0; t < NTIME; ++t) {
        u64 acc[4] = {};

        if (t > 0) {
            #pragma unroll 4
            for (int k = 0; k < NS; k += 4) {
                ulonglong2 B  = *(const ulonglong2*)(bp  + k);
                ulonglong2 A0 = *(const ulonglong2*)(ap0 + k);
                ulonglong2 A1 = *(const ulonglong2*)(ap1 + k);
                ulonglong2 A2 = *(const ulonglong2*)(ap2 + k);
                ulonglong2 A3 = *(const ulonglong2*)(ap3 + k);
                fma2(acc[0], A0.x, B.x); fma2(acc[0], A0.y, B.y);
                fma2(acc[1], A1.x, B.x); fma2(acc[1], A1.y, B.y);
                fma2(acc[2], A2.x, B.x); fma2(acc[2], A2.y, B.y);
                fma2(acc[3], A3.x, B.x); fma2(acc[3], A3.y, B.y);
            }
        }

        // epilogue: tanh(acc + fin_t) -> states log (this IS the state)
        #pragma unroll
        for (int i = 0; i < 4; ++i) {
            float v = tanhf(hadd2(acc[i]) + ffin[i]);
            g_states[(rr[i] * NTIME + t) * NS + c] = v;
        }
        __syncthreads();          // CTA-wide h-b: all STGs precede the release

        if (t + 1 < NTIME) {
            int* bar = &g_bar[(t * NROWT + rowtile) * BARPAD];
            if (tid == 0) {
                arrive_release(bar);             // release-arrive (group of 8)
            }
            // -- prefetch fin(t+1), overlapped with peers' arrival --
            #pragma unroll
            for (int i = 0; i < 4; ++i)
                ffin[i] = __ldcg(&g_fin[(rr[i] * NTIME + t + 1) * NS + c]);
            if (tid == 0) {
                while (ld_acq(bar) < NCOLT) { }
            }
            __syncthreads();

            // stage states[t] for this rowtile (written by the 8 group blocks)
            #pragma unroll
            for (int s = tid; s < 16 * 128; s += 256) {
                int row = s >> 7, q4 = (s & 127) << 2;
                float4 v = __ldcg((const float4*)
                    &g_states[((rb0 + row) * NTIME + t) * NS + q4]);
                *(float4*)&As[row * 520 + q4] = v;
            }
            __syncthreads();
        }
    }
}

// =====================================================================
// Phase 3: y[bt][a] = dot(states[bt], W_out[a]) + b_out[a]
// =====================================================================
__global__ void __launch_bounds__(256)
out_kernel(const float* __restrict__ W_out,
           const float* __restrict__ b_out,
           float* __restrict__ y) {
    __shared__ float As[64 * 36];
    __shared__ float Bs[64 * 33];

    int tid = threadIdx.x;
    int tx = tid & 15, ty = tid >> 4;
    int bt0 = blockIdx.x * 64;
    int a0  = blockIdx.y * 64;

    float acc[4][4] = {};

    for (int kc = 0; kc < NS; kc += 32) {
        for (int s = tid; s < 512; s += 256) {
            int row = s >> 3, q = (s & 7) << 2;
            float4 v = *(const float4*)&g_states[(bt0 + row) * NS + kc + q];
            *(float4*)&As[row * 36 + q] = v;
        }
        for (int s = tid; s < 512; s += 256) {
            int row = s >> 3, q = (s & 7) << 2;
            float4 v = *(const float4*)&W_out[(a0 + row) * NS + kc + q];
            float* d = &Bs[row * 33 + q];
            d[0] = v.x; d[1] = v.y; d[2] = v.z; d[3] = v.w;
        }
        __syncthreads();
        #pragma unroll
        for (int k = 0; k < 32; ++k) {
            float a[4], b[4];
            #pragma unroll
            for (int i = 0; i < 4; ++i) a[i] = As[(ty + 16 * i) * 36 + k];
            #pragma unroll
            for (int j = 0; j < 4; ++j) b[j] = Bs[(tx + 16 * j) * 33 + k];
            #pragma unroll
            for (int i = 0; i < 4; ++i)
                #pragma unroll
                for (int j = 0; j < 4; ++j)
                    acc[i][j] = fmaf(a[i], b[j], acc[i][j]);
        }
        __syncthreads();
    }

    #pragma unroll
    for (int i = 0; i < 4; ++i) {
        int r = bt0 + ty + 16 * i;
        #pragma unroll
        for (int j = 0; j < 4; ++j) {
            int c = a0 + tx + 16 * j;
            y[r * NALPH + c] = acc[i][j] + b_out[c];
        }
    }
}

// =====================================================================
// launch
// =====================================================================
extern "C" void kernel_launch(void* const* d_in, const int* in_sizes, int n_in,
                              void* d_out, int out_size) {
    const int*   w     = (const int*)  d_in[0];
    const float* emb   = (const float*)d_in[1];
    const float* W_in  = (const float*)d_in[2];
    const float* b_in  = (const float*)d_in[3];
    const float* W_out = (const float*)d_in[4];
    const float* b_out = (const float*)d_in[5];
    float* y = (float*)d_out;

    size_t rnn_smem = (size_t)(64 * 516 + 16 * 520) * sizeof(float);
    cudaFuncSetAttribute(rnn_kernel,
                         cudaFuncAttributeMaxDynamicSharedMemorySize,
                         (int)rnn_smem);

    reset_kernel<<<(NTIME * NROWT * BARPAD + 255) / 256, 256>>>();
    fin_kernel<<<dim3(BT / 64, NS / 64), 256>>>(w, emb, W_in, b_in);
    rnn_kernel<<<128, 256, rnn_smem>>>(W_in);
    out_kernel<<<dim3(BT / 64, NALPH / 64), 256>>>(W_out, b_out, y);
}